// round 16
// baseline (speedup 1.0000x reference)
#include <cuda_runtime.h>
#include <cstdint>

// out[b,h,w,c] = (vector[0,c] >= -5) ? ip1[b,h,w,c] : ip2[b,h,w,c]
// Fixed shape: 16,777,216 f32 = 4,194,304 float4 = 2048 blocks x 256 thr x 8.
//
// R16: software-pipelined hot path. Same speculative structure as the 17.8us
// winner (4-deep load prologue overlapping the mask fetch), but the epilogue
// interleaves store(i) with load(i+4), capping the live payload at ~5 float4
// instead of 8 -> fewer regs, higher occupancy, same traffic and MLP window.

static constexpr int THREADS = 256;
static constexpr int VPT = 8;                       // float4 per thread
static constexpr int N4 = 32 * 64 * 64 * 128 / 4;   // 4,194,304
static constexpr int BLOCKS = N4 / (THREADS * VPT); // 2048, exact

__global__ __launch_bounds__(THREADS)
void random_pick_kernel(const float4* __restrict__ ip1,
                        const float4* __restrict__ ip2,
                        const float* __restrict__ vec,
                        float4* __restrict__ out)
{
    int base = blockIdx.x * (THREADS * VPT) + threadIdx.x;
    int g = base & 31;  // fixed channel group (stride 256 == 0 mod 32)

    // Prologue: 4 speculative loads in flight; mask fetch overlaps.
    float4 r[VPT];
    #pragma unroll
    for (int i = 0; i < 4; i++)
        r[i] = __ldcg(ip1 + base + i * THREADS);

    float4 v = __ldg(reinterpret_cast<const float4*>(vec) + g);
    bool m0 = v.x >= -5.0f;
    bool m1 = v.y >= -5.0f;
    bool m2 = v.z >= -5.0f;
    bool m3 = v.w >= -5.0f;

    if (m0 & m1 & m2 & m3) {
        // Hot path (probability ~1): pipelined store(i) / load(i+4).
        #pragma unroll
        for (int i = 0; i < 4; i++) {
            r[i + 4] = __ldcg(ip1 + base + (i + 4) * THREADS);
            out[base + i * THREADS] = r[i];
        }
        #pragma unroll
        for (int i = 4; i < VPT; i++)
            out[base + i * THREADS] = r[i];
    } else {
        // Cold path (probability ~0 for N(0,1) vector).
        #pragma unroll
        for (int i = 4; i < VPT; i++)
            r[i] = __ldcg(ip1 + base + i * THREADS);
        if (!(m0 | m1 | m2 | m3)) {
            #pragma unroll
            for (int i = 0; i < VPT; i++)
                r[i] = __ldcg(ip2 + base + i * THREADS);
        } else {
            #pragma unroll
            for (int i = 0; i < VPT; i++) {
                float4 b = __ldcg(ip2 + base + i * THREADS);
                r[i].x = m0 ? r[i].x : b.x;
                r[i].y = m1 ? r[i].y : b.y;
                r[i].z = m2 ? r[i].z : b.z;
                r[i].w = m3 ? r[i].w : b.w;
            }
        }
        #pragma unroll
        for (int i = 0; i < VPT; i++)
            out[base + i * THREADS] = r[i];
    }
}

extern "C" void kernel_launch(void* const* d_in, const int* in_sizes, int n_in,
                              void* d_out, int out_size)
{
    const float4* ip1 = reinterpret_cast<const float4*>(d_in[0]);
    const float4* ip2 = reinterpret_cast<const float4*>(d_in[1]);
    const float*  vec = reinterpret_cast<const float*>(d_in[2]);  // row 0 used
    float4* out = reinterpret_cast<float4*>(d_out);

    random_pick_kernel<<<BLOCKS, THREADS>>>(ip1, ip2, vec, out);
}

// round 17
// speedup vs baseline: 1.0242x; 1.0242x over previous
#include <cuda_runtime.h>
#include <cstdint>

// out[b,h,w,c] = (vector[0,c] >= -5) ? ip1[b,h,w,c] : ip2[b,h,w,c]
// Fixed shape: 16,777,216 f32 = 4,194,304 float4 = 2048 blocks x 256 thr x 8.
//
// FINAL (locked; best kernel 17.79/17.95/18.14us across three runs of this
// exact source). The mandatory 64 MiB read + 64 MiB write mixed HBM stream is
// the floor: LDG, 256-bit LDG, TMA bulk and CE memcpy all converge to the
// same ~4.5-4.7 TB/s DRAM equilibrium (path-independent); cache-policy
// matrix, eviction hints, occupancy shaping and software pipelining are all
// flat-to-negative. Winning structure:
//   - exact tiling, no bounds checks (shape compile-time fixed)
//   - 8 speculative __ldcg loads issued BEFORE the mask resolves (removes the
//     vec-load -> branch -> data-load serial chain; mask ~always selects ip1)
//   - plain .wb stores (best-measured store policy)
//   - thread stride 256 == 0 mod 32 -> fixed float4 channel group per thread

static constexpr int THREADS = 256;
static constexpr int VPT = 8;                       // float4 per thread
static constexpr int N4 = 32 * 64 * 64 * 128 / 4;   // 4,194,304
static constexpr int BLOCKS = N4 / (THREADS * VPT); // 2048, exact

__global__ __launch_bounds__(THREADS)
void random_pick_kernel(const float4* __restrict__ ip1,
                        const float4* __restrict__ ip2,
                        const float* __restrict__ vec,
                        float4* __restrict__ out)
{
    int base = blockIdx.x * (THREADS * VPT) + threadIdx.x;
    int g = base & 31;  // fixed channel group (stride 256 == 0 mod 32)

    // Speculative: issue all 8 data loads immediately; mask load overlaps.
    float4 r[VPT];
    #pragma unroll
    for (int i = 0; i < VPT; i++)
        r[i] = __ldcg(ip1 + base + i * THREADS);

    float4 v = __ldg(reinterpret_cast<const float4*>(vec) + g);
    bool m0 = v.x >= -5.0f;
    bool m1 = v.y >= -5.0f;
    bool m2 = v.z >= -5.0f;
    bool m3 = v.w >= -5.0f;

    if (!(m0 & m1 & m2 & m3)) {
        // Cold path (probability ~0 for N(0,1) vector).
        if (!(m0 | m1 | m2 | m3)) {
            #pragma unroll
            for (int i = 0; i < VPT; i++)
                r[i] = __ldcg(ip2 + base + i * THREADS);
        } else {
            #pragma unroll
            for (int i = 0; i < VPT; i++) {
                float4 b = __ldcg(ip2 + base + i * THREADS);
                r[i].x = m0 ? r[i].x : b.x;
                r[i].y = m1 ? r[i].y : b.y;
                r[i].z = m2 ? r[i].z : b.z;
                r[i].w = m3 ? r[i].w : b.w;
            }
        }
    }

    // Plain .wb stores (best-measured policy).
    #pragma unroll
    for (int i = 0; i < VPT; i++)
        out[base + i * THREADS] = r[i];
}

extern "C" void kernel_launch(void* const* d_in, const int* in_sizes, int n_in,
                              void* d_out, int out_size)
{
    const float4* ip1 = reinterpret_cast<const float4*>(d_in[0]);
    const float4* ip2 = reinterpret_cast<const float4*>(d_in[1]);
    const float*  vec = reinterpret_cast<const float*>(d_in[2]);  // row 0 used
    float4* out = reinterpret_cast<float4*>(d_out);

    random_pick_kernel<<<BLOCKS, THREADS>>>(ip1, ip2, vec, out);
}